// round 4
// baseline (speedup 1.0000x reference)
#include <cuda_runtime.h>
#include <cstddef>

#define NNODES   10000
#define NEDGES   160000
#define NETOT    170000   // + self loops
#define HMAX     8

// ---------------- scratch (device globals; no allocation allowed) ----------
__device__ float g_hx [NNODES * 512];   // W-transformed features of current layer
__device__ float g_f1 [NNODES * 512];   // layer0 output
__device__ float g_f2 [NNODES * 512];   // layer1 output
__device__ float g_als[NNODES * HMAX];
__device__ float g_ald[NNODES * HMAX];
__device__ int   g_deg[NNODES];
__device__ int   g_off[NNODES + 1];
__device__ int   g_cur[NNODES];
__device__ int   g_csr_src[NETOT];

// ---------------- CSR build ------------------------------------------------
__global__ void zero_deg_kernel() {
    int i = blockIdx.x * blockDim.x + threadIdx.x;
    if (i < NNODES) g_deg[i] = 0;
}

__global__ void count_kernel(const int* __restrict__ ei) {
    int i = blockIdx.x * blockDim.x + threadIdx.x;
    if (i >= NETOT) return;
    int dst = (i < NEDGES) ? ei[NEDGES + i] : (i - NEDGES);
    atomicAdd(&g_deg[dst], 1);
}

__global__ void scan_kernel() {
    __shared__ int sm[1024];
    int tid = threadIdx.x;
    const int SEG = (NNODES + 1023) / 1024;   // 10
    int beg = tid * SEG;
    int end = beg + SEG; if (end > NNODES) end = NNODES;
    int s = 0;
    for (int i = beg; i < end; i++) s += g_deg[i];
    sm[tid] = s;
    __syncthreads();
    // Hillis-Steele inclusive scan
    for (int d = 1; d < 1024; d <<= 1) {
        int v = (tid >= d) ? sm[tid - d] : 0;
        __syncthreads();
        sm[tid] += v;
        __syncthreads();
    }
    int run = (tid > 0) ? sm[tid - 1] : 0;   // exclusive prefix of my segment
    for (int i = beg; i < end; i++) {
        g_off[i] = run;
        g_cur[i] = run;
        run += g_deg[i];
    }
    if (tid == 1023) g_off[NNODES] = sm[1023];
}

__global__ void scatter_kernel(const int* __restrict__ ei) {
    int i = blockIdx.x * blockDim.x + threadIdx.x;
    if (i >= NETOT) return;
    int src, dst;
    if (i < NEDGES) { src = ei[i]; dst = ei[NEDGES + i]; }
    else            { src = i - NEDGES; dst = src; }
    int p = atomicAdd(&g_cur[dst], 1);
    g_csr_src[p] = src;
}

// ---------------- GEMM: C[M,Ncol] = A[M,K] @ B[K,Ncol] ---------------------
// 128x128 tile, 256 threads, 8x8 microtile, K-tile 8
__global__ __launch_bounds__(256) void gemm128_kernel(
    const float* __restrict__ A, const float* __restrict__ B,
    float* __restrict__ C, int M, int K, int Ncol)
{
    __shared__ float As[8][132];
    __shared__ float Bs[8][128];
    int tid = threadIdx.x;
    int tx = tid & 15, ty = tid >> 4;
    int row0 = blockIdx.x * 128;
    int col0 = blockIdx.y * 128;

    int am = tid >> 1;            // 0..127 (row within tile)
    int ak = (tid & 1) * 4;       // 0 or 4
    int bk = tid >> 5;            // 0..7
    int bc = (tid & 31) * 4;      // 0..124

    float acc[8][8];
#pragma unroll
    for (int i = 0; i < 8; i++)
#pragma unroll
        for (int j = 0; j < 8; j++) acc[i][j] = 0.f;

    for (int k0 = 0; k0 < K; k0 += 8) {
        float4 av = make_float4(0.f, 0.f, 0.f, 0.f);
        int ar = row0 + am;
        if (ar < M) av = *(const float4*)(A + (size_t)ar * K + k0 + ak);
        As[ak + 0][am] = av.x; As[ak + 1][am] = av.y;
        As[ak + 2][am] = av.z; As[ak + 3][am] = av.w;

        float4 bv = make_float4(0.f, 0.f, 0.f, 0.f);
        int bcg = col0 + bc;
        if (bcg < Ncol)  // Ncol % 4 == 0 always here
            bv = *(const float4*)(B + (size_t)(k0 + bk) * Ncol + bcg);
        *(float4*)&Bs[bk][bc] = bv;
        __syncthreads();

#pragma unroll
        for (int kk = 0; kk < 8; kk++) {
            float af[8], bf[8];
#pragma unroll
            for (int i = 0; i < 8; i++) af[i] = As[kk][ty + 16 * i];
#pragma unroll
            for (int j = 0; j < 8; j++) bf[j] = Bs[kk][tx + 16 * j];
#pragma unroll
            for (int i = 0; i < 8; i++)
#pragma unroll
                for (int j = 0; j < 8; j++) acc[i][j] += af[i] * bf[j];
        }
        __syncthreads();
    }

#pragma unroll
    for (int i = 0; i < 8; i++) {
        int r = row0 + ty + 16 * i;
        if (r >= M) continue;
#pragma unroll
        for (int j = 0; j < 8; j++) {
            int c = col0 + tx + 16 * j;
            if (c < Ncol) C[(size_t)r * Ncol + c] = acc[i][j];
        }
    }
}

// 64x64 tile, 256 threads, 4x4 microtile, K-tile 16 (for skinny Ncol)
__global__ __launch_bounds__(256) void gemm64_kernel(
    const float* __restrict__ A, const float* __restrict__ B,
    float* __restrict__ C, int M, int K, int Ncol)
{
    __shared__ float As[16][68];
    __shared__ float Bs[16][64];
    int tid = threadIdx.x;
    int tx = tid & 15, ty = tid >> 4;
    int row0 = blockIdx.x * 64;
    int col0 = blockIdx.y * 64;

    int am = tid >> 2;            // 0..63
    int ak = (tid & 3) * 4;       // 0,4,8,12
    int bk = tid >> 4;            // 0..15
    int bc = (tid & 15) * 4;      // 0..60

    float acc[4][4];
#pragma unroll
    for (int i = 0; i < 4; i++)
#pragma unroll
        for (int j = 0; j < 4; j++) acc[i][j] = 0.f;

    for (int k0 = 0; k0 < K; k0 += 16) {
        float4 av = make_float4(0.f, 0.f, 0.f, 0.f);
        int ar = row0 + am;
        if (ar < M) av = *(const float4*)(A + (size_t)ar * K + k0 + ak);
        As[ak + 0][am] = av.x; As[ak + 1][am] = av.y;
        As[ak + 2][am] = av.z; As[ak + 3][am] = av.w;

        float4 bv = make_float4(0.f, 0.f, 0.f, 0.f);
        int bcg = col0 + bc;
        if (bcg < Ncol)
            bv = *(const float4*)(B + (size_t)(k0 + bk) * Ncol + bcg);
        *(float4*)&Bs[bk][bc] = bv;
        __syncthreads();

#pragma unroll
        for (int kk = 0; kk < 16; kk++) {
            float af[4], bf[4];
#pragma unroll
            for (int i = 0; i < 4; i++) af[i] = As[kk][ty + 16 * i];
#pragma unroll
            for (int j = 0; j < 4; j++) bf[j] = Bs[kk][tx + 16 * j];
#pragma unroll
            for (int i = 0; i < 4; i++)
#pragma unroll
                for (int j = 0; j < 4; j++) acc[i][j] += af[i] * bf[j];
        }
        __syncthreads();
    }

#pragma unroll
    for (int i = 0; i < 4; i++) {
        int r = row0 + ty + 16 * i;
        if (r >= M) continue;
#pragma unroll
        for (int j = 0; j < 4; j++) {
            int c = col0 + tx + 16 * j;
            if (c < Ncol) C[(size_t)r * Ncol + c] = acc[i][j];
        }
    }
}

// ---------------- attention logits: al_s/al_d [N,H] ------------------------
// one warp per (node, head)
__global__ void logits_kernel(const float* __restrict__ hx,
                              const float* __restrict__ a_src,
                              const float* __restrict__ a_dst,
                              float* __restrict__ als, float* __restrict__ ald,
                              int H, int C)
{
    int n = blockIdx.x;
    int warp = threadIdx.x >> 5;
    int lane = threadIdx.x & 31;
    if (warp >= H) return;
    const float* row = hx + (size_t)n * H * C + warp * C;
    float ss = 0.f, sd = 0.f;
    for (int c = lane; c < C; c += 32) {
        float v = row[c];
        ss += v * a_src[warp * C + c];
        sd += v * a_dst[warp * C + c];
    }
#pragma unroll
    for (int s = 16; s > 0; s >>= 1) {
        ss += __shfl_down_sync(0xffffffffu, ss, s);
        sd += __shfl_down_sync(0xffffffffu, sd, s);
    }
    if (lane == 0) {
        als[n * H + warp] = ss;
        ald[n * H + warp] = sd;
    }
}

// ---------------- per-dst softmax + aggregation ----------------------------
// block (256 thr) per dst node; no global atomics
__global__ __launch_bounds__(256) void aggregate_kernel(
    const float* __restrict__ hx,
    const float* __restrict__ als, const float* __restrict__ ald,
    const float* __restrict__ bias, float* __restrict__ out,
    int H, int C, int act)
{
    int n   = blockIdx.x;
    int HC  = H * C;
    int tid = threadIdx.x;
    int h   = tid % H;        // H divides 256 (8 or 1)
    int w   = tid / H;
    int NW  = 256 / H;

    __shared__ float sm_ald[HMAX];
    __shared__ float scratch[256];
    __shared__ float sm_alpha[256];
    __shared__ int   sm_src[256];

    int e0  = g_off[n];
    int deg = g_off[n + 1] - e0;

    if (tid < H) sm_ald[tid] = ald[(size_t)n * H + tid];
    __syncthreads();
    float myald = sm_ald[h];

    // phase 1: max over incoming edges (per head)
    float mx = -1e30f;
    for (int j = w; j < deg; j += NW) {
        int s = g_csr_src[e0 + j];
        float v = als[(size_t)s * H + h] + myald;
        v = (v >= 0.f) ? v : 0.2f * v;
        mx = fmaxf(mx, v);
    }
    scratch[tid] = mx;
    __syncthreads();
    for (int st = NW >> 1; st > 0; st >>= 1) {
        if (w < st) scratch[tid] = fmaxf(scratch[tid], scratch[tid + st * H]);
        __syncthreads();
    }
    float m = scratch[h];
    __syncthreads();

    // phase 2: sum of exp
    float sum = 0.f;
    for (int j = w; j < deg; j += NW) {
        int s = g_csr_src[e0 + j];
        float v = als[(size_t)s * H + h] + myald;
        v = (v >= 0.f) ? v : 0.2f * v;
        sum += expf(v - m);
    }
    scratch[tid] = sum;
    __syncthreads();
    for (int st = NW >> 1; st > 0; st >>= 1) {
        if (w < st) scratch[tid] += scratch[tid + st * H];
        __syncthreads();
    }
    float denom = scratch[h] + 1e-16f;
    __syncthreads();

    // phase 3: weighted aggregation, chunks of NW edges
    float acc0 = 0.f, acc1 = 0.f;
    int c0 = tid, c1 = tid + 256;
    int h0 = (c0 < HC) ? (c0 / C) : 0;
    int h1 = (c1 < HC) ? (c1 / C) : 0;

    for (int base = 0; base < deg; base += NW) {
        int j = base + w;
        if (j < deg) {
            int s = g_csr_src[e0 + j];
            if (h == 0) sm_src[w] = s;
            float v = als[(size_t)s * H + h] + myald;
            v = (v >= 0.f) ? v : 0.2f * v;
            sm_alpha[w * H + h] = expf(v - m) / denom;
        }
        __syncthreads();
        int lim = deg - base; if (lim > NW) lim = NW;
        for (int j2 = 0; j2 < lim; j2++) {
            int s = sm_src[j2];
            const float* hrow = hx + (size_t)s * HC;
            float a0 = sm_alpha[j2 * H + h0];
            float a1 = sm_alpha[j2 * H + h1];
            if (c0 < HC) acc0 += hrow[c0] * a0;
            if (c1 < HC) acc1 += hrow[c1] * a1;
        }
        __syncthreads();
    }

    if (c0 < HC) {
        float o = acc0 + bias[c0];
        if (act) o = (o > 0.f) ? o : expm1f(o);
        out[(size_t)n * HC + c0] = o;
    }
    if (c1 < HC) {
        float o = acc1 + bias[c1];
        if (act) o = (o > 0.f) ? o : expm1f(o);
        out[(size_t)n * HC + c1] = o;
    }
}

// ---------------- host -----------------------------------------------------
extern "C" void kernel_launch(void* const* d_in, const int* in_sizes, int n_in,
                              void* d_out, int out_size)
{
    const float* x      = (const float*)d_in[0];
    const int*   ei     = (const int*)  d_in[1];
    const float* W0     = (const float*)d_in[2];
    const float* a_src0 = (const float*)d_in[3];
    const float* a_dst0 = (const float*)d_in[4];
    const float* b0     = (const float*)d_in[5];
    const float* W1     = (const float*)d_in[6];
    const float* a_src1 = (const float*)d_in[7];
    const float* a_dst1 = (const float*)d_in[8];
    const float* b1     = (const float*)d_in[9];
    const float* W2     = (const float*)d_in[10];
    const float* a_src2 = (const float*)d_in[11];
    const float* a_dst2 = (const float*)d_in[12];
    const float* b2     = (const float*)d_in[13];
    float* out = (float*)d_out;

    float *hx, *f1, *f2, *als, *ald;
    cudaGetSymbolAddress((void**)&hx,  g_hx);
    cudaGetSymbolAddress((void**)&f1,  g_f1);
    cudaGetSymbolAddress((void**)&f2,  g_f2);
    cudaGetSymbolAddress((void**)&als, g_als);
    cudaGetSymbolAddress((void**)&ald, g_ald);

    // CSR build (by dst)
    zero_deg_kernel<<<(NNODES + 255) / 256, 256>>>();
    count_kernel<<<(NETOT + 255) / 256, 256>>>(ei);
    scan_kernel<<<1, 1024>>>();
    scatter_kernel<<<(NETOT + 255) / 256, 256>>>(ei);

    // ---- layer 0: 256 -> 8x64, ELU
    {
        dim3 grid((NNODES + 127) / 128, (512 + 127) / 128);
        gemm128_kernel<<<grid, 256>>>(x, W0, hx, NNODES, 256, 512);
        logits_kernel<<<NNODES, 256>>>(hx, a_src0, a_dst0, als, ald, 8, 64);
        aggregate_kernel<<<NNODES, 256>>>(hx, als, ald, b0, f1, 8, 64, 1);
    }
    // ---- layer 1: 512 -> 8x64, ELU
    {
        dim3 grid((NNODES + 127) / 128, (512 + 127) / 128);
        gemm128_kernel<<<grid, 256>>>(f1, W1, hx, NNODES, 512, 512);
        logits_kernel<<<NNODES, 256>>>(hx, a_src1, a_dst1, als, ald, 8, 64);
        aggregate_kernel<<<NNODES, 256>>>(hx, als, ald, b1, f2, 8, 64, 1);
    }
    // ---- layer 2: 512 -> 1x40, no activation, write d_out
    {
        dim3 grid((NNODES + 63) / 64, (40 + 63) / 64);
        gemm64_kernel<<<grid, 256>>>(f2, W2, hx, NNODES, 512, 40);
        logits_kernel<<<NNODES, 32>>>(hx, a_src2, a_dst2, als, ald, 1, 40);
        aggregate_kernel<<<NNODES, 256>>>(hx, als, ald, b2, out, 1, 40, 0);
    }
    (void)in_sizes; (void)n_in; (void)out_size;
}